// round 1
// baseline (speedup 1.0000x reference)
#include <cuda_runtime.h>
#include <cuda_bf16.h>

#define BATCH 1024
#define NN    8192
#define NB    8
#define TOTAL_IN 512

#define TB 32   // batch tile per block
#define TN 32   // neuron tile per block
// 256 threads = 16(tx: neuron) x 16(ty: batch); micro-tile 2b x 2n x 8k per thread

__global__ __launch_bounds__(256)
void dendrite_kernel(const float* __restrict__ inputs,    // [B,512]
                     const float* __restrict__ bw,        // [N,8,64]
                     const float* __restrict__ g_syn,     // [B,N,8]
                     const float* __restrict__ plateaus,  // [B,N,8]
                     const float* __restrict__ g_e,       // [B,N]
                     const float* __restrict__ v_mem,     // [B,N]
                     float* __restrict__ out)             // [2,B,N]: spikes then v
{
    const float SYN_DECAY     = 0.99335550625f;  // exp(-0.1/15)
    const float PLATEAU_DECAY = 0.99875078085f;  // exp(-0.1/80)
    const float E_DECAY       = 0.98019867331f;  // exp(-0.1/5)

    __shared__ float x_s[64][TB + 1];   // [i][b], +1 pad to break store conflicts
    __shared__ float w_s[64][TN + 1];   // [i][n]

    const int tid = threadIdx.x;
    const int tx  = tid & 15;   // neuron group
    const int ty  = tid >> 4;   // batch group
    const int n0  = blockIdx.x * TN;
    const int b0  = blockIdx.y * TB;

    const int ic = tid & 15;    // float4 column index within 64-wide k slice
    const int rr = tid >> 4;    // row 0..15 (two passes cover 32 rows)

    float acc[NB][2][2];
    #pragma unroll
    for (int k = 0; k < NB; k++)
        #pragma unroll
        for (int a = 0; a < 2; a++)
            #pragma unroll
            for (int c = 0; c < 2; c++) acc[k][a][c] = 0.f;

    #pragma unroll
    for (int k = 0; k < NB; k++) {
        __syncthreads();
        // stage x (transposed) and relu'd w (transposed) for this branch
        #pragma unroll
        for (int p = 0; p < 2; p++) {
            const int row = rr + p * 16;
            float4 xv = *(const float4*)&inputs[(size_t)(b0 + row) * TOTAL_IN + k * 64 + ic * 4];
            x_s[ic * 4 + 0][row] = xv.x;
            x_s[ic * 4 + 1][row] = xv.y;
            x_s[ic * 4 + 2][row] = xv.z;
            x_s[ic * 4 + 3][row] = xv.w;
            float4 wv = *(const float4*)&bw[(size_t)(n0 + row) * TOTAL_IN + k * 64 + ic * 4];
            w_s[ic * 4 + 0][row] = fmaxf(wv.x, 0.f);
            w_s[ic * 4 + 1][row] = fmaxf(wv.y, 0.f);
            w_s[ic * 4 + 2][row] = fmaxf(wv.z, 0.f);
            w_s[ic * 4 + 3][row] = fmaxf(wv.w, 0.f);
        }
        __syncthreads();

        #pragma unroll 16
        for (int i = 0; i < 64; i++) {
            const float xa0 = x_s[i][ty * 2 + 0];
            const float xa1 = x_s[i][ty * 2 + 1];
            const float wb0 = w_s[i][tx * 2 + 0];
            const float wb1 = w_s[i][tx * 2 + 1];
            acc[k][0][0] = fmaf(xa0, wb0, acc[k][0][0]);
            acc[k][0][1] = fmaf(xa0, wb1, acc[k][0][1]);
            acc[k][1][0] = fmaf(xa1, wb0, acc[k][1][0]);
            acc[k][1][1] = fmaf(xa1, wb1, acc[k][1][1]);
        }
    }

    // ---- elementwise neuron state update + output ----
    #pragma unroll
    for (int rb = 0; rb < 2; rb++) {
        #pragma unroll
        for (int rn = 0; rn < 2; rn++) {
            const int b = b0 + ty * 2 + rb;
            const int n = n0 + tx * 2 + rn;
            const size_t idx = (size_t)b * NN + n;

            const float4* gsp = (const float4*)(g_syn + idx * NB);
            const float4* plp = (const float4*)(plateaus + idx * NB);
            float4 gA = gsp[0], gB = gsp[1];
            float4 pA = plp[0], pB = plp[1];
            float gsv[8] = {gA.x, gA.y, gA.z, gA.w, gB.x, gB.y, gB.z, gB.w};
            float plv[8] = {pA.x, pA.y, pA.z, pA.w, pB.x, pB.y, pB.z, pB.w};

            float soma = 0.f;
            #pragma unroll
            for (int k = 0; k < NB; k++) {
                const float g = fmaf(SYN_DECAY, gsv[k], acc[k][rb][rn]);
                const bool supra = g > 0.3f;
                const float nmda = g * (supra ? 3.0f : 0.8f);
                float p = PLATEAU_DECAY * plv[k];
                if (supra) p = fmaxf(p, nmda);
                const float total = nmda + p;
                // 2*tanh(total/2) == 2*(1-e^-total)/(1+e^-total)
                const float e = __expf(-total);
                soma += 2.0f * __fdividef(1.0f - e, 1.0f + e);
            }

            const float gev = fmaf(E_DECAY, g_e[idx], soma);
            const float v0  = v_mem[idx];
            float v = v0 + 0.005f * (gev * (3.0f - v0) - v0);
            const float spike = (v >= 1.0f) ? 1.0f : 0.0f;
            if (v >= 1.0f) v = 0.0f;
            out[idx] = spike;
            out[(size_t)BATCH * NN + idx] = v;
        }
    }
}

extern "C" void kernel_launch(void* const* d_in, const int* in_sizes, int n_in,
                              void* d_out, int out_size) {
    const float* inputs   = (const float*)d_in[0];
    const float* bw       = (const float*)d_in[1];
    const float* g_syn    = (const float*)d_in[2];
    const float* plateaus = (const float*)d_in[3];
    const float* g_e      = (const float*)d_in[4];
    const float* v_mem    = (const float*)d_in[5];
    float* out = (float*)d_out;

    dim3 grid(NN / TN, BATCH / TB);  // 256 x 32 blocks
    dendrite_kernel<<<grid, 256>>>(inputs, bw, g_syn, plateaus, g_e, v_mem, out);
}

// round 3
// speedup vs baseline: 3.6630x; 3.6630x over previous
#include <cuda_runtime.h>
#include <cuda_bf16.h>
#include <cstdint>

#define BATCH 1024
#define NN    8192
#define NB    8
#define TOTAL_IN 512

// Fragment-order scratch (bf16), filled by prep kernel.
// xfrag: [64 mtiles][32 ks][32 lanes] x uint4  (a0,a1,a2,a3)  = 1 MB
// wfrag: [1024 ntiles][32 ks][32 lanes] x uint2 (b0,b1)        = 8 MB
__device__ uint4 g_xfrag[64 * 32 * 32];
__device__ uint2 g_wfrag[1024 * 32 * 32];

__device__ __forceinline__ uint32_t pack_bf2(float lo, float hi) {
    __nv_bfloat162 h = __floats2bfloat162_rn(lo, hi);
    return *reinterpret_cast<uint32_t*>(&h);
}

// ---------------- prep: permute into mma fragment order ----------------
__global__ __launch_bounds__(256)
void prep_kernel(const float* __restrict__ x, const float* __restrict__ w) {
    const int NXF = 64 * 32 * 32;        // 65536
    const int NWF = 1024 * 32 * 32;      // 1048576
    int i = blockIdx.x * blockDim.x + threadIdx.x;
    if (i < NXF) {
        int lane = i & 31, ks = (i >> 5) & 31, mt = i >> 10;
        int k = ks >> 2, s = ks & 3, g = lane >> 2, q = lane & 3;
        int kk = k * 64 + s * 16;
        const float* xr0 = x + (size_t)(mt * 16 + g) * TOTAL_IN + kk + 2 * q;
        const float* xr1 = xr0 + 8 * TOTAL_IN;
        float2 v00 = *(const float2*)xr0;
        float2 v10 = *(const float2*)xr1;
        float2 v01 = *(const float2*)(xr0 + 8);
        float2 v11 = *(const float2*)(xr1 + 8);
        uint4 o;
        o.x = pack_bf2(v00.x, v00.y);   // a0: (g,   2q..2q+1)
        o.y = pack_bf2(v10.x, v10.y);   // a1: (g+8, 2q..)
        o.z = pack_bf2(v01.x, v01.y);   // a2: (g,   2q+8..)
        o.w = pack_bf2(v11.x, v11.y);   // a3: (g+8, 2q+8..)
        g_xfrag[i] = o;
    } else if (i - NXF < NWF) {
        int j = i - NXF;
        int lane = j & 31, ks = (j >> 5) & 31, nt = j >> 10;
        int k = ks >> 2, s = ks & 3, g = lane >> 2, q = lane & 3;
        int kk = k * 64 + s * 16;
        const float* wr = w + (size_t)(nt * 8 + g) * TOTAL_IN + kk + 2 * q;
        float2 u0 = *(const float2*)wr;
        float2 u1 = *(const float2*)(wr + 8);
        uint2 o;
        o.x = pack_bf2(fmaxf(u0.x, 0.f), fmaxf(u0.y, 0.f));  // b0: k=2q,2q+1, n=g
        o.y = pack_bf2(fmaxf(u1.x, 0.f), fmaxf(u1.y, 0.f));  // b1: k=2q+8,2q+9
        g_wfrag[j] = o;
    }
}

__device__ __forceinline__ void mma_bf16(float acc[4], const uint4& a, const uint2& b) {
    asm volatile(
        "mma.sync.aligned.m16n8k16.row.col.f32.bf16.bf16.f32 "
        "{%0,%1,%2,%3}, {%4,%5,%6,%7}, {%8,%9}, {%0,%1,%2,%3};"
        : "+f"(acc[0]), "+f"(acc[1]), "+f"(acc[2]), "+f"(acc[3])
        : "r"(a.x), "r"(a.y), "r"(a.z), "r"(a.w), "r"(b.x), "r"(b.y));
}

// ---------------- main fused kernel ----------------
// CTA: 256 threads = 8 warps. Tile: M=16 (batch), N=64 (neurons; 8 per warp).
// grid = (8192/64, 1024/16) = (128, 64)
__global__ __launch_bounds__(256)
void dendrite_main(const float* __restrict__ g_syn,
                   const float* __restrict__ plateaus,
                   const float* __restrict__ g_e,
                   const float* __restrict__ v_mem,
                   float* __restrict__ out)
{
    const float SYN_DECAY     = 0.99335550625f;  // exp(-0.1/15)
    const float PLATEAU_DECAY = 0.99875078085f;  // exp(-0.1/80)
    const float E_DECAY       = 0.98019867331f;  // exp(-0.1/5)

    const int tid = threadIdx.x;
    const int w = tid >> 5, lane = tid & 31;
    const int mt = blockIdx.y;
    const int nt8 = blockIdx.x * 8 + w;          // 8-neuron tile index

    const uint4* xf = g_xfrag + (size_t)(mt * 32) * 32 + lane;
    const uint2* wf = g_wfrag + (size_t)(nt8 * 32) * 32 + lane;

    float acc[NB][4];
    #pragma unroll
    for (int k = 0; k < NB; k++)
        #pragma unroll
        for (int j = 0; j < 4; j++) acc[k][j] = 0.f;

    #pragma unroll
    for (int ks = 0; ks < 32; ks++) {
        uint4 a = xf[ks * 32];
        uint2 b = wf[ks * 32];
        mma_bf16(acc[ks >> 2], a, b);
    }

    // ---- fused elementwise epilogue ----
    const int g = lane >> 2, q = lane & 3;
    const int n = nt8 * 8 + 2 * q;               // this thread's 2 neuron cols

    #pragma unroll
    for (int h = 0; h < 2; h++) {
        const int b = mt * 16 + g + h * 8;
        const size_t base = (size_t)b * NN + n;

        // state for cols n and n+1 (each 8 branches = 32B)
        const float4* gp0 = (const float4*)(g_syn + base * NB);
        const float4* pp0 = (const float4*)(plateaus + base * NB);
        float4 gsA = gp0[0], gsB = gp0[1], gsC = gp0[2], gsD = gp0[3];
        float4 plA = pp0[0], plB = pp0[1], plC = pp0[2], plD = pp0[3];
        float2 ge2 = *(const float2*)(g_e + base);
        float2 vm2 = *(const float2*)(v_mem + base);

        float gs[2][8] = {{gsA.x, gsA.y, gsA.z, gsA.w, gsB.x, gsB.y, gsB.z, gsB.w},
                          {gsC.x, gsC.y, gsC.z, gsC.w, gsD.x, gsD.y, gsD.z, gsD.w}};
        float pl[2][8] = {{plA.x, plA.y, plA.z, plA.w, plB.x, plB.y, plB.z, plB.w},
                          {plC.x, plC.y, plC.z, plC.w, plD.x, plD.y, plD.z, plD.w}};
        float gev[2] = {ge2.x, ge2.y};
        float vmv[2] = {vm2.x, vm2.y};
        float spk[2], vo[2];

        #pragma unroll
        for (int j = 0; j < 2; j++) {
            float soma = 0.f;
            #pragma unroll
            for (int k = 0; k < NB; k++) {
                const float gv = fmaf(SYN_DECAY, gs[j][k], acc[k][2 * h + j]);
                const bool supra = gv > 0.3f;
                const float nmda = gv * (supra ? 3.0f : 0.8f);
                float p = PLATEAU_DECAY * pl[j][k];
                if (supra) p = fmaxf(p, nmda);
                // 2*tanh(t/2) = 2*(1-e^-t)/(1+e^-t)
                const float e = __expf(-(nmda + p));
                soma += 2.0f * __fdividef(1.0f - e, 1.0f + e);
            }
            const float ge_n = fmaf(E_DECAY, gev[j], soma);
            float v = vmv[j] + 0.005f * (ge_n * (3.0f - vmv[j]) - vmv[j]);
            spk[j] = (v >= 1.0f) ? 1.0f : 0.0f;
            vo[j]  = (v >= 1.0f) ? 0.0f : v;
        }
        *(float2*)(out + base) = make_float2(spk[0], spk[1]);
        *(float2*)(out + (size_t)BATCH * NN + base) = make_float2(vo[0], vo[1]);
    }
}

extern "C" void kernel_launch(void* const* d_in, const int* in_sizes, int n_in,
                              void* d_out, int out_size) {
    const float* inputs   = (const float*)d_in[0];
    const float* bw       = (const float*)d_in[1];
    const float* g_syn    = (const float*)d_in[2];
    const float* plateaus = (const float*)d_in[3];
    const float* g_e      = (const float*)d_in[4];
    const float* v_mem    = (const float*)d_in[5];
    float* out = (float*)d_out;

    const int NTOT = 64 * 32 * 32 + 1024 * 32 * 32;   // 1,114,112
    prep_kernel<<<(NTOT + 255) / 256, 256>>>(inputs, bw);

    dim3 grid(NN / 64, BATCH / 16);   // (128, 64)
    dendrite_main<<<grid, 256>>>(g_syn, plateaus, g_e, v_mem, out);
}